// round 2
// baseline (speedup 1.0000x reference)
#include <cuda_runtime.h>

// MultiScaleProcessor: images[64,256,256,3] f32 -> out[64,4,256,256,3] f32
// Scales (sorted): 32, 64, 128, 256. Each resized bilinearly (linspace coords,
// edge-clamped) then zero-padded centered to 256x256. Scale 256 = passthrough.
//
// Layout facts exploited:
//   - one output row = 768 floats = 192 float4, 16B-aligned
//   - pad boundaries in floats (3*p, 3*(p+s)) are multiples of 4 for all scales,
//     so each float4 is entirely-zero or entirely-data -> STG.128 everywhere.
//   - each block processes ROWS_PER_BLK output rows (amortize scheduling,
//     MLP on the store path).

#define ROWS_PER_BLK 2

__global__ void __launch_bounds__(192) msp_kernel(const float* __restrict__ in,
                                                  float* __restrict__ out) {
    const int t   = threadIdx.x;                 // float4 index within row 0..191
    const int yb  = blockIdx.x * ROWS_PER_BLK;   // first row of this block
    const int si  = blockIdx.y;                  // 0..3  (scale = 32<<si)
    const int b   = blockIdx.z;                  // 0..63

    const int s = 32 << si;
    const int p = (256 - s) >> 1;

    const float* ib = in + (size_t)b * (256 * 256 * 3);
    float4* obase = reinterpret_cast<float4*>(
        out + (((size_t)b * 4 + si) * 256) * 768);

    const float fac = 255.0f / (float)(s - 1);
    const int g0 = 4 * t;          // first float index this thread owns in a row
    const int lo = 3 * p;          // data region [lo, hi) in floats
    const int hi = 3 * (p + s);

    // Per-thread x-interp constants are row-invariant: precompute once.
    int   x0k[4], x1k[4], ck[4];
    float wxk[4];
    const bool in_band = (g0 >= lo) & (g0 < hi);
    if (si != 3 && in_band) {
#pragma unroll
        for (int k = 0; k < 4; k++) {
            const int rel = g0 + k - lo;
            const int xx  = rel / 3;
            ck[k]  = rel - 3 * xx;
            const float fx = (float)xx * fac;
            const int x0 = (int)fx;
            wxk[k] = fx - (float)x0;
            x0k[k] = x0 * 3 + ck[k];
            x1k[k] = min(x0 + 1, 255) * 3 + ck[k];
        }
    }

    const float4 z = make_float4(0.f, 0.f, 0.f, 0.f);

#pragma unroll
    for (int r = 0; r < ROWS_PER_BLK; r++) {
        const int y = yb + r;
        float4* orow = obase + (size_t)y * 192;

        if (si == 3) {
            const float4* irow = reinterpret_cast<const float4*>(ib + y * 768);
            orow[t] = irow[t];
            continue;
        }
        if (y < p || y >= p + s || !in_band) { orow[t] = z; continue; }

        // bilinear y setup (matches jnp.linspace(0, 255, s) coords)
        const int   iy = y - p;
        const float fy = (float)iy * fac;
        const int   y0 = (int)fy;
        const float wy = fy - (float)y0;
        const int   y1 = min(y0 + 1, 255);

        const float* __restrict__ r0 = ib + y0 * 768;
        const float* __restrict__ r1 = ib + y1 * 768;

        float res[4];
#pragma unroll
        for (int k = 0; k < 4; k++) {
            const float a  = __ldg(r0 + x0k[k]);
            const float bb = __ldg(r0 + x1k[k]);
            const float cc = __ldg(r1 + x0k[k]);
            const float d  = __ldg(r1 + x1k[k]);
            const float top = a  + (bb - a ) * wxk[k];
            const float bot = cc + (d  - cc) * wxk[k];
            res[k] = top + (bot - top) * wy;
        }
        orow[t] = make_float4(res[0], res[1], res[2], res[3]);
    }
}

extern "C" void kernel_launch(void* const* d_in, const int* in_sizes, int n_in,
                              void* d_out, int out_size) {
    const float* in = (const float*)d_in[0];
    float* out = (float*)d_out;
    dim3 grid(256 / ROWS_PER_BLK, 4, 64);
    msp_kernel<<<grid, 192>>>(in, out);
}